// round 14
// baseline (speedup 1.0000x reference)
#include <cuda_runtime.h>
#include <math.h>

#define NB 32
#define TT 518
#define NF 64
#define NG 512
#define CC 128
#define CW 768
#define L2C 516
#define VD 32
#define L3 512
#define L4 510

typedef unsigned long long u64;

__device__ float d_xg[NB * TT * NG];
__device__ float d_X[NB * CC * TT];
__device__ float d_wave[NB * CW * TT];
__device__ float d_st1[CW * 2];
__device__ float d_w2t[3 * 128 * CW];   // [k'][co][ci], BN1-folded
__device__ float d_b2p[128];
__device__ float d_c2[NB * 128 * L2C];
__device__ float d_st2[128 * 2];
__device__ float d_w3t[128 * VD * 5];   // [ci][co*5+k], BN2-folded
__device__ float d_b3p[VD];
__device__ float d_c3[NB * VD * L3];
__device__ float d_st3[VD * 2];
__device__ float d_w4t[16 * 32 * 3];    // BN3-folded conv4 weights
__device__ float d_b4p[16];
__device__ float d_dwt[NB * 5 * L3];
__device__ float d_P4[NB * 16], d_Q4[NB * 16];
__device__ float d_P5[NB * 16], d_Q5[NB * 16];

__device__ __forceinline__ float sigf(float x) {
    return __fdividef(1.f, 1.f + __expf(-x));
}
__device__ __forceinline__ float tanhfast(float x) {
    return 1.f - __fdividef(2.f, __expf(2.f * x) + 1.f);
}

// ---------- 0) zero stat accumulators + conv2 bias base ----------
__global__ __launch_bounds__(256) void k_zero()
{
    int i = threadIdx.x;
    for (int j = i; j < CW * 2; j += 256) d_st1[j] = 0.f;
    if (i < 256) d_st2[i] = 0.f;
    if (i < 64) d_st3[i] = 0.f;
    if (i < 128) d_b2p[i] = 0.f;
}

// ---------- 1) input projection ----------
__global__ __launch_bounds__(256) void k_proj(
    const float* __restrict__ x,
    const float* __restrict__ wif, const float* __restrict__ wir,
    const float* __restrict__ bf, const float* __restrict__ br)
{
    __shared__ float As[64 * 64];
    __shared__ float Bs[64 * 68];
    const int tid = threadIdx.x;
    const int m0 = blockIdx.x * 64, n0 = blockIdx.y * 64;
#pragma unroll
    for (int i = 0; i < 16; i++) {
        int idx = tid + i * 256;
        int k = idx >> 6, m = idx & 63;
        int mg = m0 + m, b = mg / TT, t = mg - b * TT;
        As[k * 64 + m] = x[(b * NF + k) * TT + t];
    }
#pragma unroll
    for (int i = 0; i < 16; i++) {
        int idx = tid + i * 256;
        int n = idx >> 6, k = idx & 63;
        int ng = n0 + n;
        Bs[k * 68 + n] = (ng < 256) ? wif[ng * 64 + k] : wir[(ng - 256) * 64 + k];
    }
    __syncthreads();
    const int mb = (tid >> 4) * 4, nb = (tid & 15) * 4;
    float acc[4][4];
#pragma unroll
    for (int i = 0; i < 4; i++)
#pragma unroll
        for (int j = 0; j < 4; j++) acc[i][j] = 0.f;
#pragma unroll
    for (int k = 0; k < 64; k++) {
        float4 a = *(const float4*)&As[k * 64 + mb];
        float4 bv = *(const float4*)&Bs[k * 68 + nb];
        float am[4] = {a.x, a.y, a.z, a.w};
        float bn[4] = {bv.x, bv.y, bv.z, bv.w};
#pragma unroll
        for (int mi = 0; mi < 4; mi++)
#pragma unroll
            for (int ni = 0; ni < 4; ni++) acc[mi][ni] += am[mi] * bn[ni];
    }
    float bvr[4];
#pragma unroll
    for (int ni = 0; ni < 4; ni++) {
        int ng = n0 + nb + ni;
        bvr[ni] = (ng < 256) ? bf[ng] : br[ng - 256];
    }
#pragma unroll
    for (int mi = 0; mi < 4; mi++) {
        int mg = m0 + mb + mi;
        float4 o = {acc[mi][0] + bvr[0], acc[mi][1] + bvr[1],
                    acc[mi][2] + bvr[2], acc[mi][3] + bvr[3]};
        *(float4*)&d_xg[(size_t)mg * NG + n0 + nb] = o;
    }
}

// ---------- 2) LSTM recurrence (packed f32x2, round-5 form) ----------
__global__ __launch_bounds__(256) void k_lstm(
    const float* __restrict__ whf, const float* __restrict__ whr)
{
    const int b = blockIdx.x, dir = blockIdx.y, tid = threadIdx.x;
    const float* __restrict__ whh = dir ? whr : whf;

    u64 w2[32];
    {
        const float2* wrow = (const float2*)(whh + tid * 64);
#pragma unroll
        for (int j = 0; j < 32; j++) {
            float2 p = wrow[j];
            asm("mov.b64 %0, {%1,%2};" : "=l"(w2[j]) : "f"(p.x), "f"(p.y));
        }
    }

    __shared__ __align__(16) float h_sh[64];
    __shared__ float g_sh[256];
    if (tid < 64) h_sh[tid] = 0.f;
    float c = 0.f;
    __syncthreads();

    const float* __restrict__ xg = d_xg + (size_t)b * TT * NG + dir * 256;
    int t = dir ? (TT - 1) : 0;
    const int dt = dir ? -1 : 1;
    float xv = xg[(size_t)t * NG + tid];

    for (int s = 0; s < TT; s++) {
        float xn = (s < TT - 1) ? xg[(size_t)(t + dt) * NG + tid] : 0.f;

        u64 acc0, acc1 = 0ULL;
        asm("mov.b64 %0, {%1,%2};" : "=l"(acc0) : "f"(xv), "f"(0.f));
        const u64* h2 = (const u64*)h_sh;
#pragma unroll
        for (int j = 0; j < 32; j += 2) {
            u64 hv0 = h2[j], hv1 = h2[j + 1];
            asm("fma.rn.f32x2 %0, %1, %2, %0;" : "+l"(acc0) : "l"(w2[j]), "l"(hv0));
            asm("fma.rn.f32x2 %0, %1, %2, %0;" : "+l"(acc1) : "l"(w2[j + 1]), "l"(hv1));
        }
        float a0, a1, b0, b1;
        asm("mov.b64 {%0,%1}, %2;" : "=f"(a0), "=f"(a1) : "l"(acc0));
        asm("mov.b64 {%0,%1}, %2;" : "=f"(b0), "=f"(b1) : "l"(acc1));
        g_sh[tid] = (a0 + b0) + (a1 + b1);
        __syncthreads();

        if (tid < 64) {
            float gi = g_sh[tid], gf = g_sh[64 + tid];
            float gg = g_sh[128 + tid], go = g_sh[192 + tid];
            c = sigf(gf) * c + sigf(gi) * tanhfast(gg);
            float h = sigf(go) * tanhfast(c);
            h_sh[tid] = h;
            d_X[((size_t)b * CC + dir * 64 + tid) * TT + t] = h;
        }
        __syncthreads();
        xv = xn;
        t += dt;
    }
}

// ---------- 3) wave module: 2 positions/thread (measured best) + BN1 stats ----------
__global__ __launch_bounds__(128) void k_wave(
    const float* __restrict__ bw, const float* __restrict__ bb)
{
    __shared__ float xr[532];
    __shared__ float sw[90];
    __shared__ float sb[6];
    __shared__ float sRed[12];
    const int b = blockIdx.x, ch = blockIdx.y, tid = threadIdx.x;
    if (tid < 90) sw[tid] = bw[tid];
    if (tid < 6) sb[tid] = bb[tid];
    if (tid < 12) sRed[tid] = 0.f;
    const float* __restrict__ Xr = d_X + ((size_t)b * CC + ch) * TT;
    for (int i = tid; i < 532; i += 128) {
        int t = i - 7;
        xr[i] = (t >= 0 && t < TT) ? Xr[t] : 0.f;
    }
    __syncthreads();

    float zs[6], zq[6];
#pragma unroll
    for (int ii = 0; ii < 6; ii++) { zs[ii] = 0.f; zq[ii] = 0.f; }

    float* __restrict__ wrow = d_wave + ((size_t)b * CW + ch) * TT;

    for (int tb = tid * 2; tb < TT; tb += 256) {
        float win[16];
#pragma unroll
        for (int k = 0; k < 16; k++) win[k] = xr[tb + k];
        float pA[8], pB[8];
        pA[0] = win[7];
        pB[0] = win[8];
#pragma unroll
        for (int m = 1; m < 8; m++) {
            pA[m] = win[7 + m] + win[7 - m];
            pB[m] = win[8 + m] + win[8 - m];
        }
#pragma unroll 1
        for (int ii = 0; ii < 6; ii++) {
            float bias = sb[ii];
            float sA = bias, sB = bias;
#pragma unroll
            for (int k = 0; k < 15; k++) {
                float w = sw[ii * 15 + k];
                sA += win[k] * w;
                sB += win[k + 1] * w;
            }
            sA = fmaxf(sA, 0.f);
            sB = fmaxf(sB, 0.f);
            const float fscale = (6.283185307179586f / 15.f) * (float)(ii + 1);
            float cA = __cosf(fscale * sA);
            float cB = __cosf(fscale * sB);
            float oA = pA[0] + pA[1] * cA;
            float oB = pB[0] + pB[1] * cB;
            float cpA = cA, cppA = 1.f, cpB = cB, cppB = 1.f;
            float twoA = 2.f * cA, twoB = 2.f * cB;
#pragma unroll
            for (int m = 2; m < 8; m++) {
                float cmA = twoA * cpA - cppA;
                float cmB = twoB * cpB - cppB;
                oA += pA[m] * cmA;
                oB += pB[m] * cmB;
                cppA = cpA; cpA = cmA;
                cppB = cpB; cpB = cmB;
            }
            float qA = (truncf(sA * 15.f) + 1.f) * (2.f / 17.f);
            float qB = (truncf(sB * 15.f) + 1.f) * (2.f / 17.f);
            float zA = oA * rsqrtf(qA);
            float zB = oB * rsqrtf(qB);
            float* wr = wrow + (size_t)(ii * CC) * TT;
            wr[tb] = zA;
            wr[tb + 1] = zB;
            zs[ii] += zA + zB;
            zq[ii] += zA * zA + zB * zB;
        }
    }
    const int lane = tid & 31;
#pragma unroll
    for (int ii = 0; ii < 6; ii++) {
        float v1 = zs[ii], v2 = zq[ii];
#pragma unroll
        for (int o = 16; o > 0; o >>= 1) {
            v1 += __shfl_xor_sync(0xffffffffu, v1, o);
            v2 += __shfl_xor_sync(0xffffffffu, v2, o);
        }
        if (lane == 0) {
            atomicAdd(&sRed[ii * 2], v1);
            atomicAdd(&sRed[ii * 2 + 1], v2);
        }
    }
    __syncthreads();
    if (tid < 12)
        atomicAdd(&d_st1[2 * ((tid >> 1) * CC + ch) + (tid & 1)], sRed[tid]);
}

// ---------- fold BN1 into conv2, split over (co, k') ----------
__global__ __launch_bounds__(256) void k_fold2(
    const float* __restrict__ g1, const float* __restrict__ be1,
    const float* __restrict__ w2, const float* __restrict__ b2)
{
    const int co = blockIdx.x, k = blockIdx.y, tid = threadIdx.x;
    const float invN = 1.f / (float)(NB * TT);
    float acc = 0.f;
#pragma unroll
    for (int r = 0; r < 3; r++) {
        int ci = tid + r * 256;
        float m = d_st1[2 * ci] * invN;
        float v = d_st1[2 * ci + 1] * invN - m * m;
        float s = g1[ci] * rsqrtf(v + 1e-5f);
        float tt = be1[ci] - m * s;
        float wv = w2[(size_t)co * (CW * 3) + ci * 3 + k];
        d_w2t[(size_t)k * (128 * CW) + co * CW + ci] = wv * s;
        acc += wv * tt;
    }
    const int lane = tid & 31, wrp = tid >> 5;
#pragma unroll
    for (int o = 16; o > 0; o >>= 1) acc += __shfl_xor_sync(0xffffffffu, acc, o);
    __shared__ float red[8];
    if (lane == 0) red[wrp] = acc;
    __syncthreads();
    if (tid == 0) {
        float s = red[0] + red[1] + red[2] + red[3] + red[4] + red[5] + red[6] + red[7];
        if (k == 0) s += b2[co];
        atomicAdd(&d_b2p[co], s);
    }
}

// ---------- fold BN2 into conv3 ([ci][co*5+k] layout) ----------
__global__ __launch_bounds__(256) void k_fold3(
    const float* __restrict__ g2, const float* __restrict__ be2,
    const float* __restrict__ w3, const float* __restrict__ b3)
{
    __shared__ float s2[128], t2[128];
    const int co = blockIdx.x, tid = threadIdx.x;
    const float invN = 1.f / (float)(NB * L2C);
    if (tid < 128) {
        float m = d_st2[2 * tid] * invN;
        float v = d_st2[2 * tid + 1] * invN - m * m;
        float s = g2[tid] * rsqrtf(v + 1e-5f);
        s2[tid] = s;
        t2[tid] = be2[tid] - m * s;
    }
    __syncthreads();
    float acc = 0.f;
    for (int idx = tid; idx < 128 * 5; idx += 256) {
        int ci = idx / 5, k = idx - ci * 5;
        float wv = w3[(size_t)co * 640 + idx];
        d_w3t[(size_t)ci * 160 + co * 5 + k] = wv * s2[ci];
        acc += wv * t2[ci];
    }
    __shared__ float red[256];
    red[tid] = acc;
    __syncthreads();
    for (int o = 128; o > 0; o >>= 1) {
        if (tid < o) red[tid] += red[tid + o];
        __syncthreads();
    }
    if (tid == 0) d_b3p[co] = b3[co] + red[0];
}

// ---------- fold BN3 into conv4 weights ----------
__global__ __launch_bounds__(256) void k_fold4(
    const float* __restrict__ g3, const float* __restrict__ be3,
    const float* __restrict__ w4, const float* __restrict__ b4)
{
    __shared__ float s3[32], t3[32], bacc[16];
    const int tid = threadIdx.x;
    const float invN = 1.f / (float)(NB * L3);
    if (tid < 32) {
        float m = d_st3[2 * tid] * invN;
        float v = d_st3[2 * tid + 1] * invN - m * m;
        float s = g3[tid] * rsqrtf(v + 1e-5f);
        s3[tid] = s;
        t3[tid] = be3[tid] - m * s;
    }
    if (tid < 16) bacc[tid] = 0.f;
    __syncthreads();
    for (int i = tid; i < 1536; i += 256) {
        int ci = (i / 3) & 31, co = i / 96;
        float wv = w4[i];
        d_w4t[i] = wv * s3[ci];
        atomicAdd(&bacc[co], wv * t3[ci]);
    }
    __syncthreads();
    if (tid < 16) d_b4p[tid] = b4[tid] + bacc[tid];
}

// ---------- conv2 via tf32 mma.sync + relu + BN2 stats (R9 form) ----------
__global__ __launch_bounds__(256, 2) void k_conv2()
{
    __shared__ float As[128 * 36];
    __shared__ float Bs[32 * 72];
    __shared__ float sP2[128], sQ2[128];
    const int tid = threadIdx.x;
    const int wid = tid >> 5, lane = tid & 31;
    const int t0 = blockIdx.x * 64, b = blockIdx.y;
    const int mg = wid >> 1, ng = wid & 1;
    const int gr = lane >> 2, c = lane & 3;
    if (tid < 128) { sP2[tid] = 0.f; sQ2[tid] = 0.f; }

    float d[2][4][4];
#pragma unroll
    for (int mt = 0; mt < 2; mt++)
#pragma unroll
        for (int nt = 0; nt < 4; nt++)
#pragma unroll
            for (int r = 0; r < 4; r++) d[mt][nt][r] = 0.f;

    const float* __restrict__ wavB = d_wave + (size_t)b * CW * TT;
    const int ldco = tid >> 1, ldci = (tid & 1) * 16;
    const int ldn = tid & 63, ldk0 = (tid >> 6) * 8;
    const int tld = t0 + ldn;

    for (int kp = 0; kp < 3; kp++) {
        for (int cc = 0; cc < 24; cc++) {
            const int ci0 = cc * 32;
            __syncthreads();
            {
                const float4* src = (const float4*)&d_w2t[(size_t)kp * (128 * CW) + ldco * CW + ci0 + ldci];
                float4* dst = (float4*)&As[ldco * 36 + ldci];
                dst[0] = src[0]; dst[1] = src[1]; dst[2] = src[2]; dst[3] = src[3];
            }
            {
                int t = tld + kp;
                bool ok = (t < TT);
#pragma unroll
                for (int p = 0; p < 8; p++) {
                    int k = ldk0 + p;
                    Bs[k * 72 + ldn] = ok ? wavB[(size_t)(ci0 + k) * TT + t] : 0.f;
                }
            }
            __syncthreads();

            unsigned aR[2][2][8];
#pragma unroll
            for (int mt = 0; mt < 2; mt++) {
                int r0 = (mg * 32 + mt * 16 + gr) * 36 + c;
#pragma unroll
                for (int u = 0; u < 8; u++) {
                    aR[mt][0][u] = __float_as_uint(As[r0 + 4 * u]);
                    aR[mt][1][u] = __float_as_uint(As[r0 + 8 * 36 + 4 * u]);
                }
            }
#pragma unroll
            for (int s = 0; s < 4; s++) {
                unsigned bb[4][2];
#pragma unroll
                for (int nt = 0; nt < 4; nt++) {
                    int nn = ng * 32 + nt * 8 + gr;
                    bb[nt][0] = __float_as_uint(Bs[(c + 8 * s) * 72 + nn]);
                    bb[nt][1] = __float_as_uint(Bs[(c + 8 * s + 4) * 72 + nn]);
                }
#pragma unroll
                for (int mt = 0; mt < 2; mt++)
#pragma unroll
                    for (int nt = 0; nt < 4; nt++)
                        asm volatile(
                            "mma.sync.aligned.m16n8k8.row.col.f32.tf32.tf32.f32 "
                            "{%0,%1,%2,%3}, {%4,%5,%6,%7}, {%8,%9}, {%0,%1,%2,%3};"
                            : "+f"(d[mt][nt][0]), "+f"(d[mt][nt][1]),
                              "+f"(d[mt][nt][2]), "+f"(d[mt][nt][3])
                            : "r"(aR[mt][0][2 * s]), "r"(aR[mt][1][2 * s]),
                              "r"(aR[mt][0][2 * s + 1]), "r"(aR[mt][1][2 * s + 1]),
                              "r"(bb[nt][0]), "r"(bb[nt][1]));
            }
        }
    }

#pragma unroll
    for (int mt = 0; mt < 2; mt++) {
        int coA = mg * 32 + mt * 16 + gr;
        int coB = coA + 8;
        float bA = d_b2p[coA], bB = d_b2p[coB];
        float sA = 0.f, qA = 0.f, sB = 0.f, qB = 0.f;
        float* rowA = d_c2 + ((size_t)b * 128 + coA) * L2C;
        float* rowB = d_c2 + ((size_t)b * 128 + coB) * L2C;
#pragma unroll
        for (int nt = 0; nt < 4; nt++) {
            int tg = t0 + ng * 32 + nt * 8 + 2 * c;
            if (tg < L2C) {
                float z0 = fmaxf(d[mt][nt][0] + bA, 0.f);
                float z2 = fmaxf(d[mt][nt][2] + bB, 0.f);
                rowA[tg] = z0; rowB[tg] = z2;
                sA += z0; qA += z0 * z0;
                sB += z2; qB += z2 * z2;
            }
            if (tg + 1 < L2C) {
                float z1 = fmaxf(d[mt][nt][1] + bA, 0.f);
                float z3 = fmaxf(d[mt][nt][3] + bB, 0.f);
                rowA[tg + 1] = z1; rowB[tg + 1] = z3;
                sA += z1; qA += z1 * z1;
                sB += z3; qB += z3 * z3;
            }
        }
        atomicAdd(&sP2[coA], sA);
        atomicAdd(&sQ2[coA], qA);
        atomicAdd(&sP2[coB], sB);
        atomicAdd(&sQ2[coB], qB);
    }
    __syncthreads();
    if (tid < 128) {
        atomicAdd(&d_st2[2 * tid], sP2[tid]);
        atomicAdd(&d_st2[2 * tid + 1], sQ2[tid]);
    }
}

// ---------- conv3 (128->32, k=5) scalar + relu + BN3 stats ----------
__global__ __launch_bounds__(256) void k_conv3()
{
    __shared__ float xs[16 * 72];
    __shared__ float ws[16 * 160];
    __shared__ float sP3[32], sQ3[32];
    const int tid = threadIdx.x;
    const int t0 = blockIdx.x * 64, b = blockIdx.y;
    const int co_b = (tid >> 4) * 2, t_b = (tid & 15) * 4;
    if (tid < 32) { sP3[tid] = 0.f; sQ3[tid] = 0.f; }
    float acc[2][4];
#pragma unroll
    for (int i = 0; i < 2; i++)
#pragma unroll
        for (int j = 0; j < 4; j++) acc[i][j] = 0.f;

    for (int cc = 0; cc < 8; cc++) {
        for (int i = tid; i < 16 * 68; i += 256) {
            int ci = i / 68, j = i - ci * 68;
            xs[ci * 72 + j] = d_c2[((size_t)b * 128 + cc * 16 + ci) * L2C + t0 + j];
        }
        for (int i = tid; i < 2560; i += 256) {
            int ci = i / 160, r = i - ci * 160;
            ws[ci * 160 + r] = d_w3t[(size_t)(cc * 16 + ci) * 160 + r];
        }
        __syncthreads();
#pragma unroll
        for (int ci = 0; ci < 16; ci++) {
            float xv[8];
            float4 xa = *(const float4*)&xs[ci * 72 + t_b];
            float4 xb4 = *(const float4*)&xs[ci * 72 + t_b + 4];
            xv[0] = xa.x; xv[1] = xa.y; xv[2] = xa.z; xv[3] = xa.w;
            xv[4] = xb4.x; xv[5] = xb4.y; xv[6] = xb4.z; xv[7] = xb4.w;
            float wv[10];
#pragma unroll
            for (int j = 0; j < 10; j++) wv[j] = ws[ci * 160 + co_b * 5 + j];
#pragma unroll
            for (int cj = 0; cj < 2; cj++)
#pragma unroll
                for (int tj = 0; tj < 4; tj++) {
                    float s = acc[cj][tj];
#pragma unroll
                    for (int k = 0; k < 5; k++) s += wv[cj * 5 + k] * xv[tj + k];
                    acc[cj][tj] = s;
                }
        }
        __syncthreads();
    }
#pragma unroll
    for (int cj = 0; cj < 2; cj++) {
        int co = co_b + cj;
        float bias = d_b3p[co];
        float zsum = 0.f, zsq = 0.f;
#pragma unroll
        for (int tj = 0; tj < 4; tj++) {
            int t = t0 + t_b + tj;
            float z = fmaxf(acc[cj][tj] + bias, 0.f);
            d_c3[((size_t)b * VD + co) * L3 + t] = z;
            zsum += z; zsq += z * z;
        }
        atomicAdd(&sP3[co], zsum);
        atomicAdd(&sQ3[co], zsq);
    }
    __syncthreads();
    if (tid < 32) {
        atomicAdd(&d_st3[2 * tid], sP3[tid]);
        atomicAdd(&d_st3[2 * tid + 1], sQ3[tid]);
    }
}

// ---------- conv4 (32->16, k=3) + relu, pooled sums (BN3 folded in) ----------
__global__ __launch_bounds__(256) void k_conv4()
{
    __shared__ float wsh[1536];
    __shared__ float bsh[16];
    __shared__ float sP[16], sQ[16];
    const int b = blockIdx.x, tid = threadIdx.x;
    for (int i = tid; i < 1536; i += 256) wsh[i] = d_w4t[i];
    if (tid < 16) { bsh[tid] = d_b4p[tid]; sP[tid] = 0.f; sQ[tid] = 0.f; }
    __syncthreads();
    float ls[16], lq[16];
#pragma unroll
    for (int co = 0; co < 16; co++) { ls[co] = 0.f; lq[co] = 0.f; }
    for (int l = tid; l < L4; l += 256) {
        float acc[16];
#pragma unroll
        for (int co = 0; co < 16; co++) acc[co] = 0.f;
        const float* __restrict__ xb = d_c3 + (size_t)b * VD * L3 + l;
#pragma unroll 4
        for (int ci = 0; ci < 32; ci++) {
            float x0 = xb[ci * L3], x1 = xb[ci * L3 + 1], x2 = xb[ci * L3 + 2];
#pragma unroll
            for (int co = 0; co < 16; co++) {
                const float* w = &wsh[(co * 32 + ci) * 3];
                acc[co] += w[0] * x0 + w[1] * x1 + w[2] * x2;
            }
        }
#pragma unroll
        for (int co = 0; co < 16; co++) {
            float z = fmaxf(acc[co] + bsh[co], 0.f);
            ls[co] += z; lq[co] += z * z;
        }
    }
#pragma unroll
    for (int co = 0; co < 16; co++) {
        atomicAdd(&sP[co], ls[co]);
        atomicAdd(&sQ[co], lq[co]);
    }
    __syncthreads();
    if (tid < 16) { d_P4[b * 16 + tid] = sP[tid]; d_Q4[b * 16 + tid] = sQ[tid]; }
}

// ---------- DWT (BN3 applied via weighted channel-mean) ----------
__global__ __launch_bounds__(128) void k_dwt(
    const float* __restrict__ g3, const float* __restrict__ be3)
{
    __shared__ float m[512];
    __shared__ float a1[256];
    __shared__ float a2[128];
    __shared__ float a3[64];
    __shared__ float s3[32];
    __shared__ float Tsh;
    const int b = blockIdx.x, tid = threadIdx.x;
    const float invN = 1.f / (float)(NB * L3);
    if (tid < 32) {
        float mm = d_st3[2 * tid] * invN;
        float vv = d_st3[2 * tid + 1] * invN - mm * mm;
        float s = g3[tid] * rsqrtf(vv + 1e-5f);
        s3[tid] = s * (1.f / 32.f);
        float tt = be3[tid] - mm * s;
#pragma unroll
        for (int o = 16; o > 0; o >>= 1) tt += __shfl_xor_sync(0xffffffffu, tt, o);
        if (tid == 0) Tsh = tt * (1.f / 32.f);
    }
    __syncthreads();
    const float T = Tsh;
    for (int l = tid; l < 512; l += 128) {
        float s = T;
#pragma unroll 8
        for (int c = 0; c < 32; c++) s += s3[c] * d_c3[((size_t)b * VD + c) * L3 + l];
        m[l] = s;
    }
    __syncthreads();
    const float Hc = 0.7071067811865476f;
    float* __restrict__ dw = d_dwt + (size_t)b * 5 * L3;
    for (int i = tid; i < 256; i += 128) {
        float e = m[2 * i], o = m[2 * i + 1];
        a1[i] = (e + o) * Hc;
        float d = (e - o) * Hc;
        dw[4 * 512 + 2 * i] = d;
        dw[4 * 512 + 2 * i + 1] = d;
    }
    __syncthreads();
    if (tid < 128) {
        float e = a1[2 * tid], o = a1[2 * tid + 1];
        a2[tid] = (e + o) * Hc;
        float d = (e - o) * Hc;
#pragma unroll
        for (int j = 0; j < 4; j++) dw[3 * 512 + 4 * tid + j] = d;
    }
    __syncthreads();
    if (tid < 64) {
        float e = a2[2 * tid], o = a2[2 * tid + 1];
        a3[tid] = (e + o) * Hc;
        float d = (e - o) * Hc;
#pragma unroll
        for (int j = 0; j < 8; j++) dw[2 * 512 + 8 * tid + j] = d;
    }
    __syncthreads();
    if (tid < 32) {
        float e = a3[2 * tid], o = a3[2 * tid + 1];
        float a = (e + o) * Hc, d = (e - o) * Hc;
#pragma unroll
        for (int j = 0; j < 16; j++) {
            dw[16 * tid + j] = a;
            dw[512 + 16 * tid + j] = d;
        }
    }
}

// ---------- conv5 (5->16, k=3) + relu, pooled sums ----------
__global__ __launch_bounds__(256) void k_conv5(
    const float* __restrict__ w5, const float* __restrict__ b5)
{
    __shared__ float wsh[240];
    __shared__ float bsh[16];
    __shared__ float sP[16], sQ[16];
    const int b = blockIdx.x, tid = threadIdx.x;
    if (tid < 240) wsh[tid] = w5[tid];
    if (tid < 16) { bsh[tid] = b5[tid]; sP[tid] = 0.f; sQ[tid] = 0.f; }
    __syncthreads();
    float ls[16], lq[16];
#pragma unroll
    for (int co = 0; co < 16; co++) { ls[co] = 0.f; lq[co] = 0.f; }
    for (int l = tid; l < L4; l += 256) {
        float acc[16];
#pragma unroll
        for (int co = 0; co < 16; co++) acc[co] = 0.f;
        const float* __restrict__ xb = d_dwt + (size_t)b * 5 * L3 + l;
#pragma unroll
        for (int ci = 0; ci < 5; ci++) {
            float x0 = xb[ci * L3], x1 = xb[ci * L3 + 1], x2 = xb[ci * L3 + 2];
#pragma unroll
            for (int co = 0; co < 16; co++) {
                const float* w = &wsh[(co * 5 + ci) * 3];
                acc[co] += w[0] * x0 + w[1] * x1 + w[2] * x2;
            }
        }
#pragma unroll
        for (int co = 0; co < 16; co++) {
            float z = fmaxf(acc[co] + bsh[co], 0.f);
            ls[co] += z; lq[co] += z * z;
        }
    }
#pragma unroll
    for (int co = 0; co < 16; co++) {
        atomicAdd(&sP[co], ls[co]);
        atomicAdd(&sQ[co], lq[co]);
    }
    __syncthreads();
    if (tid < 16) { d_P5[b * 16 + tid] = sP[tid]; d_Q5[b * 16 + tid] = sQ[tid]; }
}

// ---------- final ----------
__global__ __launch_bounds__(512) void k_final(
    const float* __restrict__ g4, const float* __restrict__ be4,
    const float* __restrict__ g5, const float* __restrict__ be5,
    const float* __restrict__ fcw, const float* __restrict__ fcb,
    float* __restrict__ out)
{
    __shared__ float s4[16], t4[16], s5[16], t5[16], pool[512];
    const int tid = threadIdx.x;
    if (tid < 16) {
        float P = 0.f, Q = 0.f;
        for (int b = 0; b < NB; b++) { P += d_P4[b * 16 + tid]; Q += d_Q4[b * 16 + tid]; }
        const float N = (float)(NB * L4);
        float m = P / N, v = Q / N - m * m;
        float s = g4[tid] * rsqrtf(v + 1e-5f);
        s4[tid] = s;
        t4[tid] = be4[tid] - m * s;
    } else if (tid < 32) {
        int co = tid - 16;
        float P = 0.f, Q = 0.f;
        for (int b = 0; b < NB; b++) { P += d_P5[b * 16 + co]; Q += d_Q5[b * 16 + co]; }
        const float N = (float)(NB * L4);
        float m = P / N, v = Q / N - m * m;
        float s = g5[co] * rsqrtf(v + 1e-5f);
        s5[co] = s;
        t5[co] = be5[co] - m * s;
    }
    __syncthreads();
    {
        int b = tid >> 4, co = tid & 15;
        pool[tid] = (s4[co] * d_P4[b * 16 + co] + (float)L4 * t4[co]
                   + s5[co] * d_P5[b * 16 + co] + (float)L4 * t5[co]) * (1.f / (2.f * L4));
    }
    __syncthreads();
    if (tid < 320) {
        int b = tid / 10, j = tid - b * 10;
        float s = fcb[j];
#pragma unroll
        for (int co = 0; co < 16; co++) s += pool[b * 16 + co] * fcw[j * 16 + co];
        out[b * 10 + j] = s;
    }
}

extern "C" void kernel_launch(void* const* d_in, const int* in_sizes, int n_in,
                              void* d_out, int out_size)
{
    const float* x    = (const float*)d_in[0];
    const float* wif  = (const float*)d_in[1];
    const float* whf  = (const float*)d_in[2];
    const float* bf   = (const float*)d_in[3];
    const float* wir  = (const float*)d_in[4];
    const float* whr  = (const float*)d_in[5];
    const float* br   = (const float*)d_in[6];
    const float* bw   = (const float*)d_in[7];
    const float* bb   = (const float*)d_in[8];
    const float* g1   = (const float*)d_in[9];
    const float* be1  = (const float*)d_in[10];
    const float* g2   = (const float*)d_in[11];
    const float* be2  = (const float*)d_in[12];
    const float* g3   = (const float*)d_in[13];
    const float* be3  = (const float*)d_in[14];
    const float* g4   = (const float*)d_in[15];
    const float* be4  = (const float*)d_in[16];
    const float* g5   = (const float*)d_in[17];
    const float* be5  = (const float*)d_in[18];
    const float* w2   = (const float*)d_in[19];
    const float* b2   = (const float*)d_in[20];
    const float* w3   = (const float*)d_in[21];
    const float* b3   = (const float*)d_in[22];
    const float* w4   = (const float*)d_in[23];
    const float* b4   = (const float*)d_in[24];
    const float* w5   = (const float*)d_in[25];
    const float* b5   = (const float*)d_in[26];
    const float* fcw  = (const float*)d_in[27];
    const float* fcb  = (const float*)d_in[28];
    float* out = (float*)d_out;

    k_zero<<<1, 256>>>();
    k_proj<<<dim3(259, 8), 256>>>(x, wif, wir, bf, br);
    k_lstm<<<dim3(32, 2), 256>>>(whf, whr);
    k_wave<<<dim3(32, 128), 128>>>(bw, bb);
    k_fold2<<<dim3(128, 3), 256>>>(g1, be1, w2, b2);
    k_conv2<<<dim3(9, 32), 256>>>();
    k_fold3<<<32, 256>>>(g2, be2, w3, b3);
    k_conv3<<<dim3(8, 32), 256>>>();
    k_fold4<<<1, 256>>>(g3, be3, w4, b4);
    k_conv4<<<32, 256>>>();
    k_dwt<<<32, 128>>>(g3, be3);
    k_conv5<<<32, 256>>>(w5, b5);
    k_final<<<1, 512>>>(g4, be4, g5, be5, fcw, fcb, out);
}

// round 15
// speedup vs baseline: 1.0275x; 1.0275x over previous
#include <cuda_runtime.h>
#include <math.h>

#define NB 32
#define TT 518
#define NF 64
#define NG 512
#define CC 128
#define CW 768
#define L2C 516
#define VD 32
#define L3 512
#define L4 510

typedef unsigned long long u64;

__device__ float d_xg[NB * TT * NG];
__device__ float d_X[NB * CC * TT];
__device__ float d_wave[NB * CW * TT];
__device__ float d_st1[CW * 2];
__device__ float d_w2t[3 * 128 * CW];   // [k'][co][ci], BN1-folded
__device__ float d_b2p[128];
__device__ float d_c2[NB * 128 * L2C];
__device__ float d_st2[128 * 2];
__device__ float d_w3t[128 * VD * 5];   // [ci][co*5+k], BN2-folded
__device__ float d_b3p[VD];
__device__ float d_c3[NB * VD * L3];
__device__ float d_st3[VD * 2];
__device__ float d_ob[NB * VD * L3];
__device__ float d_dwt[NB * 5 * L3];
__device__ float d_P4[NB * 16], d_Q4[NB * 16];
__device__ float d_P5[NB * 16], d_Q5[NB * 16];

__device__ __forceinline__ float sigf(float x) {
    return __fdividef(1.f, 1.f + __expf(-x));
}
__device__ __forceinline__ float tanhfast(float x) {
    return 1.f - __fdividef(2.f, __expf(2.f * x) + 1.f);
}

// ---------- 0) zero stat accumulators + conv2 bias base ----------
__global__ __launch_bounds__(256) void k_zero()
{
    int i = threadIdx.x;
    for (int j = i; j < CW * 2; j += 256) d_st1[j] = 0.f;
    if (i < 256) d_st2[i] = 0.f;
    if (i < 64) d_st3[i] = 0.f;
    if (i < 128) d_b2p[i] = 0.f;
}

// ---------- 1) input projection ----------
__global__ __launch_bounds__(256) void k_proj(
    const float* __restrict__ x,
    const float* __restrict__ wif, const float* __restrict__ wir,
    const float* __restrict__ bf, const float* __restrict__ br)
{
    __shared__ float As[64 * 64];
    __shared__ float Bs[64 * 68];
    const int tid = threadIdx.x;
    const int m0 = blockIdx.x * 64, n0 = blockIdx.y * 64;
#pragma unroll
    for (int i = 0; i < 16; i++) {
        int idx = tid + i * 256;
        int k = idx >> 6, m = idx & 63;
        int mg = m0 + m, b = mg / TT, t = mg - b * TT;
        As[k * 64 + m] = x[(b * NF + k) * TT + t];
    }
#pragma unroll
    for (int i = 0; i < 16; i++) {
        int idx = tid + i * 256;
        int n = idx >> 6, k = idx & 63;
        int ng = n0 + n;
        Bs[k * 68 + n] = (ng < 256) ? wif[ng * 64 + k] : wir[(ng - 256) * 64 + k];
    }
    __syncthreads();
    const int mb = (tid >> 4) * 4, nb = (tid & 15) * 4;
    float acc[4][4];
#pragma unroll
    for (int i = 0; i < 4; i++)
#pragma unroll
        for (int j = 0; j < 4; j++) acc[i][j] = 0.f;
#pragma unroll
    for (int k = 0; k < 64; k++) {
        float4 a = *(const float4*)&As[k * 64 + mb];
        float4 bv = *(const float4*)&Bs[k * 68 + nb];
        float am[4] = {a.x, a.y, a.z, a.w};
        float bn[4] = {bv.x, bv.y, bv.z, bv.w};
#pragma unroll
        for (int mi = 0; mi < 4; mi++)
#pragma unroll
            for (int ni = 0; ni < 4; ni++) acc[mi][ni] += am[mi] * bn[ni];
    }
    float bvr[4];
#pragma unroll
    for (int ni = 0; ni < 4; ni++) {
        int ng = n0 + nb + ni;
        bvr[ni] = (ng < 256) ? bf[ng] : br[ng - 256];
    }
#pragma unroll
    for (int mi = 0; mi < 4; mi++) {
        int mg = m0 + mb + mi;
        float4 o = {acc[mi][0] + bvr[0], acc[mi][1] + bvr[1],
                    acc[mi][2] + bvr[2], acc[mi][3] + bvr[3]};
        *(float4*)&d_xg[(size_t)mg * NG + n0 + nb] = o;
    }
}

// ---------- 2) LSTM recurrence (packed f32x2, round-5 form) ----------
__global__ __launch_bounds__(256) void k_lstm(
    const float* __restrict__ whf, const float* __restrict__ whr)
{
    const int b = blockIdx.x, dir = blockIdx.y, tid = threadIdx.x;
    const float* __restrict__ whh = dir ? whr : whf;

    u64 w2[32];
    {
        const float2* wrow = (const float2*)(whh + tid * 64);
#pragma unroll
        for (int j = 0; j < 32; j++) {
            float2 p = wrow[j];
            asm("mov.b64 %0, {%1,%2};" : "=l"(w2[j]) : "f"(p.x), "f"(p.y));
        }
    }

    __shared__ __align__(16) float h_sh[64];
    __shared__ float g_sh[256];
    if (tid < 64) h_sh[tid] = 0.f;
    float c = 0.f;
    __syncthreads();

    const float* __restrict__ xg = d_xg + (size_t)b * TT * NG + dir * 256;
    int t = dir ? (TT - 1) : 0;
    const int dt = dir ? -1 : 1;
    float xv = xg[(size_t)t * NG + tid];

    for (int s = 0; s < TT; s++) {
        float xn = (s < TT - 1) ? xg[(size_t)(t + dt) * NG + tid] : 0.f;

        u64 acc0, acc1 = 0ULL;
        asm("mov.b64 %0, {%1,%2};" : "=l"(acc0) : "f"(xv), "f"(0.f));
        const u64* h2 = (const u64*)h_sh;
#pragma unroll
        for (int j = 0; j < 32; j += 2) {
            u64 hv0 = h2[j], hv1 = h2[j + 1];
            asm("fma.rn.f32x2 %0, %1, %2, %0;" : "+l"(acc0) : "l"(w2[j]), "l"(hv0));
            asm("fma.rn.f32x2 %0, %1, %2, %0;" : "+l"(acc1) : "l"(w2[j + 1]), "l"(hv1));
        }
        float a0, a1, b0, b1;
        asm("mov.b64 {%0,%1}, %2;" : "=f"(a0), "=f"(a1) : "l"(acc0));
        asm("mov.b64 {%0,%1}, %2;" : "=f"(b0), "=f"(b1) : "l"(acc1));
        g_sh[tid] = (a0 + b0) + (a1 + b1);
        __syncthreads();

        if (tid < 64) {
            float gi = g_sh[tid], gf = g_sh[64 + tid];
            float gg = g_sh[128 + tid], go = g_sh[192 + tid];
            c = sigf(gf) * c + sigf(gi) * tanhfast(gg);
            float h = sigf(go) * tanhfast(c);
            h_sh[tid] = h;
            d_X[((size_t)b * CC + dir * 64 + tid) * TT + t] = h;
        }
        __syncthreads();
        xv = xn;
        t += dt;
    }
}

// ---------- 3) wave module: 2 positions/thread (shared sw loads) + BN1 stats ----------
__global__ __launch_bounds__(128) void k_wave(
    const float* __restrict__ bw, const float* __restrict__ bb)
{
    __shared__ float xr[532];
    __shared__ float sw[90];
    __shared__ float sb[6];
    __shared__ float sRed[12];
    const int b = blockIdx.x, ch = blockIdx.y, tid = threadIdx.x;
    if (tid < 90) sw[tid] = bw[tid];
    if (tid < 6) sb[tid] = bb[tid];
    if (tid < 12) sRed[tid] = 0.f;
    const float* __restrict__ Xr = d_X + ((size_t)b * CC + ch) * TT;
    for (int i = tid; i < 532; i += 128) {
        int t = i - 7;
        xr[i] = (t >= 0 && t < TT) ? Xr[t] : 0.f;
    }
    __syncthreads();

    float zs[6], zq[6];
#pragma unroll
    for (int ii = 0; ii < 6; ii++) { zs[ii] = 0.f; zq[ii] = 0.f; }

    float* __restrict__ wrow = d_wave + ((size_t)b * CW + ch) * TT;

    // tb covers all even t in [0,516]; tb+1 <= 517 < TT always
    for (int tb = tid * 2; tb < TT; tb += 256) {
        float win[16];
#pragma unroll
        for (int k = 0; k < 16; k++) win[k] = xr[tb + k];
        float pA[8], pB[8];
        pA[0] = win[7];
        pB[0] = win[8];
#pragma unroll
        for (int m = 1; m < 8; m++) {
            pA[m] = win[7 + m] + win[7 - m];
            pB[m] = win[8 + m] + win[8 - m];
        }
#pragma unroll 1
        for (int ii = 0; ii < 6; ii++) {
            float bias = sb[ii];
            float sA = bias, sB = bias;
#pragma unroll
            for (int k = 0; k < 15; k++) {
                float w = sw[ii * 15 + k];
                sA += win[k] * w;
                sB += win[k + 1] * w;
            }
            sA = fmaxf(sA, 0.f);
            sB = fmaxf(sB, 0.f);
            const float fscale = (6.283185307179586f / 15.f) * (float)(ii + 1);
            float cA = __cosf(fscale * sA);
            float cB = __cosf(fscale * sB);
            float oA = pA[0] + pA[1] * cA;
            float oB = pB[0] + pB[1] * cB;
            float cpA = cA, cppA = 1.f, cpB = cB, cppB = 1.f;
            float twoA = 2.f * cA, twoB = 2.f * cB;
#pragma unroll
            for (int m = 2; m < 8; m++) {
                float cmA = twoA * cpA - cppA;
                float cmB = twoB * cpB - cppB;
                oA += pA[m] * cmA;
                oB += pB[m] * cmB;
                cppA = cpA; cpA = cmA;
                cppB = cpB; cpB = cmB;
            }
            float qA = (truncf(sA * 15.f) + 1.f) * (2.f / 17.f);
            float qB = (truncf(sB * 15.f) + 1.f) * (2.f / 17.f);
            float zA = oA * rsqrtf(qA);
            float zB = oB * rsqrtf(qB);
            float* wr = wrow + (size_t)(ii * CC) * TT;
            wr[tb] = zA;
            wr[tb + 1] = zB;
            zs[ii] += zA + zB;
            zq[ii] += zA * zA + zB * zB;
        }
    }
    const int lane = tid & 31;
#pragma unroll
    for (int ii = 0; ii < 6; ii++) {
        float v1 = zs[ii], v2 = zq[ii];
#pragma unroll
        for (int o = 16; o > 0; o >>= 1) {
            v1 += __shfl_xor_sync(0xffffffffu, v1, o);
            v2 += __shfl_xor_sync(0xffffffffu, v2, o);
        }
        if (lane == 0) {
            atomicAdd(&sRed[ii * 2], v1);
            atomicAdd(&sRed[ii * 2 + 1], v2);
        }
    }
    __syncthreads();
    if (tid < 12)
        atomicAdd(&d_st1[2 * ((tid >> 1) * CC + ch) + (tid & 1)], sRed[tid]);
}

// ---------- fold BN1 into conv2, split over (co, k') ----------
__global__ __launch_bounds__(256) void k_fold2(
    const float* __restrict__ g1, const float* __restrict__ be1,
    const float* __restrict__ w2, const float* __restrict__ b2)
{
    const int co = blockIdx.x, k = blockIdx.y, tid = threadIdx.x;
    const float invN = 1.f / (float)(NB * TT);
    float acc = 0.f;
#pragma unroll
    for (int r = 0; r < 3; r++) {
        int ci = tid + r * 256;
        float m = d_st1[2 * ci] * invN;
        float v = d_st1[2 * ci + 1] * invN - m * m;
        float s = g1[ci] * rsqrtf(v + 1e-5f);
        float tt = be1[ci] - m * s;
        float wv = w2[(size_t)co * (CW * 3) + ci * 3 + k];
        d_w2t[(size_t)k * (128 * CW) + co * CW + ci] = wv * s;
        acc += wv * tt;
    }
    const int lane = tid & 31, wrp = tid >> 5;
#pragma unroll
    for (int o = 16; o > 0; o >>= 1) acc += __shfl_xor_sync(0xffffffffu, acc, o);
    __shared__ float red[8];
    if (lane == 0) red[wrp] = acc;
    __syncthreads();
    if (tid == 0) {
        float s = red[0] + red[1] + red[2] + red[3] + red[4] + red[5] + red[6] + red[7];
        if (k == 0) s += b2[co];
        atomicAdd(&d_b2p[co], s);
    }
}

// ---------- fold BN2 into conv3 ([ci][co*5+k] layout) ----------
__global__ __launch_bounds__(256) void k_fold3(
    const float* __restrict__ g2, const float* __restrict__ be2,
    const float* __restrict__ w3, const float* __restrict__ b3)
{
    __shared__ float s2[128], t2[128];
    const int co = blockIdx.x, tid = threadIdx.x;
    const float invN = 1.f / (float)(NB * L2C);
    if (tid < 128) {
        float m = d_st2[2 * tid] * invN;
        float v = d_st2[2 * tid + 1] * invN - m * m;
        float s = g2[tid] * rsqrtf(v + 1e-5f);
        s2[tid] = s;
        t2[tid] = be2[tid] - m * s;
    }
    __syncthreads();
    float acc = 0.f;
    for (int idx = tid; idx < 128 * 5; idx += 256) {
        int ci = idx / 5, k = idx - ci * 5;
        float wv = w3[(size_t)co * 640 + idx];
        d_w3t[(size_t)ci * 160 + co * 5 + k] = wv * s2[ci];
        acc += wv * t2[ci];
    }
    __shared__ float red[256];
    red[tid] = acc;
    __syncthreads();
    for (int o = 128; o > 0; o >>= 1) {
        if (tid < o) red[tid] += red[tid + o];
        __syncthreads();
    }
    if (tid == 0) d_b3p[co] = b3[co] + red[0];
}

// ---------- conv2 via tf32 mma.sync + relu + BN2 stats (R9 form) ----------
__global__ __launch_bounds__(256, 2) void k_conv2()
{
    __shared__ float As[128 * 36];
    __shared__ float Bs[32 * 72];
    __shared__ float sP2[128], sQ2[128];
    const int tid = threadIdx.x;
    const int wid = tid >> 5, lane = tid & 31;
    const int t0 = blockIdx.x * 64, b = blockIdx.y;
    const int mg = wid >> 1, ng = wid & 1;
    const int gr = lane >> 2, c = lane & 3;
    if (tid < 128) { sP2[tid] = 0.f; sQ2[tid] = 0.f; }

    float d[2][4][4];
#pragma unroll
    for (int mt = 0; mt < 2; mt++)
#pragma unroll
        for (int nt = 0; nt < 4; nt++)
#pragma unroll
            for (int r = 0; r < 4; r++) d[mt][nt][r] = 0.f;

    const float* __restrict__ wavB = d_wave + (size_t)b * CW * TT;
    const int ldco = tid >> 1, ldci = (tid & 1) * 16;
    const int ldn = tid & 63, ldk0 = (tid >> 6) * 8;
    const int tld = t0 + ldn;

    for (int kp = 0; kp < 3; kp++) {
        for (int cc = 0; cc < 24; cc++) {
            const int ci0 = cc * 32;
            __syncthreads();
            {
                const float4* src = (const float4*)&d_w2t[(size_t)kp * (128 * CW) + ldco * CW + ci0 + ldci];
                float4* dst = (float4*)&As[ldco * 36 + ldci];
                dst[0] = src[0]; dst[1] = src[1]; dst[2] = src[2]; dst[3] = src[3];
            }
            {
                int t = tld + kp;
                bool ok = (t < TT);
#pragma unroll
                for (int p = 0; p < 8; p++) {
                    int k = ldk0 + p;
                    Bs[k * 72 + ldn] = ok ? wavB[(size_t)(ci0 + k) * TT + t] : 0.f;
                }
            }
            __syncthreads();

            unsigned aR[2][2][8];
#pragma unroll
            for (int mt = 0; mt < 2; mt++) {
                int r0 = (mg * 32 + mt * 16 + gr) * 36 + c;
#pragma unroll
                for (int u = 0; u < 8; u++) {
                    aR[mt][0][u] = __float_as_uint(As[r0 + 4 * u]);
                    aR[mt][1][u] = __float_as_uint(As[r0 + 8 * 36 + 4 * u]);
                }
            }
#pragma unroll
            for (int s = 0; s < 4; s++) {
                unsigned bb[4][2];
#pragma unroll
                for (int nt = 0; nt < 4; nt++) {
                    int nn = ng * 32 + nt * 8 + gr;
                    bb[nt][0] = __float_as_uint(Bs[(c + 8 * s) * 72 + nn]);
                    bb[nt][1] = __float_as_uint(Bs[(c + 8 * s + 4) * 72 + nn]);
                }
#pragma unroll
                for (int mt = 0; mt < 2; mt++)
#pragma unroll
                    for (int nt = 0; nt < 4; nt++)
                        asm volatile(
                            "mma.sync.aligned.m16n8k8.row.col.f32.tf32.tf32.f32 "
                            "{%0,%1,%2,%3}, {%4,%5,%6,%7}, {%8,%9}, {%0,%1,%2,%3};"
                            : "+f"(d[mt][nt][0]), "+f"(d[mt][nt][1]),
                              "+f"(d[mt][nt][2]), "+f"(d[mt][nt][3])
                            : "r"(aR[mt][0][2 * s]), "r"(aR[mt][1][2 * s]),
                              "r"(aR[mt][0][2 * s + 1]), "r"(aR[mt][1][2 * s + 1]),
                              "r"(bb[nt][0]), "r"(bb[nt][1]));
            }
        }
    }

#pragma unroll
    for (int mt = 0; mt < 2; mt++) {
        int coA = mg * 32 + mt * 16 + gr;
        int coB = coA + 8;
        float bA = d_b2p[coA], bB = d_b2p[coB];
        float sA = 0.f, qA = 0.f, sB = 0.f, qB = 0.f;
        float* rowA = d_c2 + ((size_t)b * 128 + coA) * L2C;
        float* rowB = d_c2 + ((size_t)b * 128 + coB) * L2C;
#pragma unroll
        for (int nt = 0; nt < 4; nt++) {
            int tg = t0 + ng * 32 + nt * 8 + 2 * c;
            if (tg < L2C) {
                float z0 = fmaxf(d[mt][nt][0] + bA, 0.f);
                float z2 = fmaxf(d[mt][nt][2] + bB, 0.f);
                rowA[tg] = z0; rowB[tg] = z2;
                sA += z0; qA += z0 * z0;
                sB += z2; qB += z2 * z2;
            }
            if (tg + 1 < L2C) {
                float z1 = fmaxf(d[mt][nt][1] + bA, 0.f);
                float z3 = fmaxf(d[mt][nt][3] + bB, 0.f);
                rowA[tg + 1] = z1; rowB[tg + 1] = z3;
                sA += z1; qA += z1 * z1;
                sB += z3; qB += z3 * z3;
            }
        }
        atomicAdd(&sP2[coA], sA);
        atomicAdd(&sQ2[coA], qA);
        atomicAdd(&sP2[coB], sB);
        atomicAdd(&sQ2[coB], qB);
    }
    __syncthreads();
    if (tid < 128) {
        atomicAdd(&d_st2[2 * tid], sP2[tid]);
        atomicAdd(&d_st2[2 * tid + 1], sQ2[tid]);
    }
}

// ---------- conv3 (128->32, k=5) scalar + relu + BN3 stats ----------
__global__ __launch_bounds__(256) void k_conv3()
{
    __shared__ float xs[16 * 72];
    __shared__ float ws[16 * 160];
    __shared__ float sP3[32], sQ3[32];
    const int tid = threadIdx.x;
    const int t0 = blockIdx.x * 64, b = blockIdx.y;
    const int co_b = (tid >> 4) * 2, t_b = (tid & 15) * 4;
    if (tid < 32) { sP3[tid] = 0.f; sQ3[tid] = 0.f; }
    float acc[2][4];
#pragma unroll
    for (int i = 0; i < 2; i++)
#pragma unroll
        for (int j = 0; j < 4; j++) acc[i][j] = 0.f;

    for (int cc = 0; cc < 8; cc++) {
        for (int i = tid; i < 16 * 68; i += 256) {
            int ci = i / 68, j = i - ci * 68;
            xs[ci * 72 + j] = d_c2[((size_t)b * 128 + cc * 16 + ci) * L2C + t0 + j];
        }
        for (int i = tid; i < 2560; i += 256) {
            int ci = i / 160, r = i - ci * 160;
            ws[ci * 160 + r] = d_w3t[(size_t)(cc * 16 + ci) * 160 + r];
        }
        __syncthreads();
#pragma unroll
        for (int ci = 0; ci < 16; ci++) {
            float xv[8];
            float4 xa = *(const float4*)&xs[ci * 72 + t_b];
            float4 xb4 = *(const float4*)&xs[ci * 72 + t_b + 4];
            xv[0] = xa.x; xv[1] = xa.y; xv[2] = xa.z; xv[3] = xa.w;
            xv[4] = xb4.x; xv[5] = xb4.y; xv[6] = xb4.z; xv[7] = xb4.w;
            float wv[10];
#pragma unroll
            for (int j = 0; j < 10; j++) wv[j] = ws[ci * 160 + co_b * 5 + j];
#pragma unroll
            for (int cj = 0; cj < 2; cj++)
#pragma unroll
                for (int tj = 0; tj < 4; tj++) {
                    float s = acc[cj][tj];
#pragma unroll
                    for (int k = 0; k < 5; k++) s += wv[cj * 5 + k] * xv[tj + k];
                    acc[cj][tj] = s;
                }
        }
        __syncthreads();
    }
#pragma unroll
    for (int cj = 0; cj < 2; cj++) {
        int co = co_b + cj;
        float bias = d_b3p[co];
        float zsum = 0.f, zsq = 0.f;
#pragma unroll
        for (int tj = 0; tj < 4; tj++) {
            int t = t0 + t_b + tj;
            float z = fmaxf(acc[cj][tj] + bias, 0.f);
            d_c3[((size_t)b * VD + co) * L3 + t] = z;
            zsum += z; zsq += z * z;
        }
        atomicAdd(&sP3[co], zsum);
        atomicAdd(&sQ3[co], zsq);
    }
    __syncthreads();
    if (tid < 32) {
        atomicAdd(&d_st3[2 * tid], sP3[tid]);
        atomicAdd(&d_st3[2 * tid + 1], sQ3[tid]);
    }
}

// ---------- apply BN3 ----------
__global__ __launch_bounds__(256) void k_bn3(
    const float* __restrict__ g3, const float* __restrict__ be3)
{
    int i = blockIdx.x * 256 + threadIdx.x;
    int c = (i >> 9) & 31;
    const float invN = 1.f / (float)(NB * L3);
    float m = d_st3[2 * c] * invN;
    float v = d_st3[2 * c + 1] * invN - m * m;
    float s = g3[c] * rsqrtf(v + 1e-5f);
    d_ob[i] = (d_c3[i] - m) * s + be3[c];
}

// ---------- conv4 (32->16, k=3) + relu, pooled sums ----------
__global__ __launch_bounds__(256) void k_conv4(
    const float* __restrict__ w4, const float* __restrict__ b4)
{
    __shared__ float wsh[1536];
    __shared__ float bsh[16];
    __shared__ float sP[16], sQ[16];
    const int b = blockIdx.x, tid = threadIdx.x;
    for (int i = tid; i < 1536; i += 256) wsh[i] = w4[i];
    if (tid < 16) { bsh[tid] = b4[tid]; sP[tid] = 0.f; sQ[tid] = 0.f; }
    __syncthreads();
    float ls[16], lq[16];
#pragma unroll
    for (int co = 0; co < 16; co++) { ls[co] = 0.f; lq[co] = 0.f; }
    for (int l = tid; l < L4; l += 256) {
        float acc[16];
#pragma unroll
        for (int co = 0; co < 16; co++) acc[co] = 0.f;
        const float* __restrict__ xb = d_ob + (size_t)b * VD * L3 + l;
#pragma unroll 4
        for (int ci = 0; ci < 32; ci++) {
            float x0 = xb[ci * L3], x1 = xb[ci * L3 + 1], x2 = xb[ci * L3 + 2];
#pragma unroll
            for (int co = 0; co < 16; co++) {
                const float* w = &wsh[(co * 32 + ci) * 3];
                acc[co] += w[0] * x0 + w[1] * x1 + w[2] * x2;
            }
        }
#pragma unroll
        for (int co = 0; co < 16; co++) {
            float z = fmaxf(acc[co] + bsh[co], 0.f);
            ls[co] += z; lq[co] += z * z;
        }
    }
#pragma unroll
    for (int co = 0; co < 16; co++) {
        atomicAdd(&sP[co], ls[co]);
        atomicAdd(&sQ[co], lq[co]);
    }
    __syncthreads();
    if (tid < 16) { d_P4[b * 16 + tid] = sP[tid]; d_Q4[b * 16 + tid] = sQ[tid]; }
}

// ---------- DWT ----------
__global__ __launch_bounds__(128) void k_dwt()
{
    __shared__ float m[512];
    __shared__ float a1[256];
    __shared__ float a2[128];
    __shared__ float a3[64];
    const int b = blockIdx.x, tid = threadIdx.x;
    for (int l = tid; l < 512; l += 128) {
        float s = 0.f;
#pragma unroll 8
        for (int c = 0; c < 32; c++) s += d_ob[((size_t)b * VD + c) * L3 + l];
        m[l] = s * (1.f / 32.f);
    }
    __syncthreads();
    const float Hc = 0.7071067811865476f;
    float* __restrict__ dw = d_dwt + (size_t)b * 5 * L3;
    for (int i = tid; i < 256; i += 128) {
        float e = m[2 * i], o = m[2 * i + 1];
        a1[i] = (e + o) * Hc;
        float d = (e - o) * Hc;
        dw[4 * 512 + 2 * i] = d;
        dw[4 * 512 + 2 * i + 1] = d;
    }
    __syncthreads();
    if (tid < 128) {
        float e = a1[2 * tid], o = a1[2 * tid + 1];
        a2[tid] = (e + o) * Hc;
        float d = (e - o) * Hc;
#pragma unroll
        for (int j = 0; j < 4; j++) dw[3 * 512 + 4 * tid + j] = d;
    }
    __syncthreads();
    if (tid < 64) {
        float e = a2[2 * tid], o = a2[2 * tid + 1];
        a3[tid] = (e + o) * Hc;
        float d = (e - o) * Hc;
#pragma unroll
        for (int j = 0; j < 8; j++) dw[2 * 512 + 8 * tid + j] = d;
    }
    __syncthreads();
    if (tid < 32) {
        float e = a3[2 * tid], o = a3[2 * tid + 1];
        float a = (e + o) * Hc, d = (e - o) * Hc;
#pragma unroll
        for (int j = 0; j < 16; j++) {
            dw[16 * tid + j] = a;
            dw[512 + 16 * tid + j] = d;
        }
    }
}

// ---------- conv5 (5->16, k=3) + relu, pooled sums ----------
__global__ __launch_bounds__(256) void k_conv5(
    const float* __restrict__ w5, const float* __restrict__ b5)
{
    __shared__ float wsh[240];
    __shared__ float bsh[16];
    __shared__ float sP[16], sQ[16];
    const int b = blockIdx.x, tid = threadIdx.x;
    if (tid < 240) wsh[tid] = w5[tid];
    if (tid < 16) { bsh[tid] = b5[tid]; sP[tid] = 0.f; sQ[tid] = 0.f; }
    __syncthreads();
    float ls[16], lq[16];
#pragma unroll
    for (int co = 0; co < 16; co++) { ls[co] = 0.f; lq[co] = 0.f; }
    for (int l = tid; l < L4; l += 256) {
        float acc[16];
#pragma unroll
        for (int co = 0; co < 16; co++) acc[co] = 0.f;
        const float* __restrict__ xb = d_dwt + (size_t)b * 5 * L3 + l;
#pragma unroll
        for (int ci = 0; ci < 5; ci++) {
            float x0 = xb[ci * L3], x1 = xb[ci * L3 + 1], x2 = xb[ci * L3 + 2];
#pragma unroll
            for (int co = 0; co < 16; co++) {
                const float* w = &wsh[(co * 5 + ci) * 3];
                acc[co] += w[0] * x0 + w[1] * x1 + w[2] * x2;
            }
        }
#pragma unroll
        for (int co = 0; co < 16; co++) {
            float z = fmaxf(acc[co] + bsh[co], 0.f);
            ls[co] += z; lq[co] += z * z;
        }
    }
#pragma unroll
    for (int co = 0; co < 16; co++) {
        atomicAdd(&sP[co], ls[co]);
        atomicAdd(&sQ[co], lq[co]);
    }
    __syncthreads();
    if (tid < 16) { d_P5[b * 16 + tid] = sP[tid]; d_Q5[b * 16 + tid] = sQ[tid]; }
}

// ---------- final ----------
__global__ __launch_bounds__(512) void k_final(
    const float* __restrict__ g4, const float* __restrict__ be4,
    const float* __restrict__ g5, const float* __restrict__ be5,
    const float* __restrict__ fcw, const float* __restrict__ fcb,
    float* __restrict__ out)
{
    __shared__ float s4[16], t4[16], s5[16], t5[16], pool[512];
    const int tid = threadIdx.x;
    if (tid < 16) {
        float P = 0.f, Q = 0.f;
        for (int b = 0; b < NB; b++) { P += d_P4[b * 16 + tid]; Q += d_Q4[b * 16 + tid]; }
        const float N = (float)(NB * L4);
        float m = P / N, v = Q / N - m * m;
        float s = g4[tid] * rsqrtf(v + 1e-5f);
        s4[tid] = s;
        t4[tid] = be4[tid] - m * s;
    } else if (tid < 32) {
        int co = tid - 16;
        float P = 0.f, Q = 0.f;
        for (int b = 0; b < NB; b++) { P += d_P5[b * 16 + co]; Q += d_Q5[b * 16 + co]; }
        const float N = (float)(NB * L4);
        float m = P / N, v = Q / N - m * m;
        float s = g5[co] * rsqrtf(v + 1e-5f);
        s5[co] = s;
        t5[co] = be5[co] - m * s;
    }
    __syncthreads();
    {
        int b = tid >> 4, co = tid & 15;
        pool[tid] = (s4[co] * d_P4[b * 16 + co] + (float)L4 * t4[co]
                   + s5[co] * d_P5[b * 16 + co] + (float)L4 * t5[co]) * (1.f / (2.f * L4));
    }
    __syncthreads();
    if (tid < 320) {
        int b = tid / 10, j = tid - b * 10;
        float s = fcb[j];
#pragma unroll
        for (int co = 0; co < 16; co++) s += pool[b * 16 + co] * fcw[j * 16 + co];
        out[b * 10 + j] = s;
    }
}

extern "C" void kernel_launch(void* const* d_in, const int* in_sizes, int n_in,
                              void* d_out, int out_size)
{
    const float* x    = (const float*)d_in[0];
    const float* wif  = (const float*)d_in[1];
    const float* whf  = (const float*)d_in[2];
    const float* bf   = (const float*)d_in[3];
    const float* wir  = (const float*)d_in[4];
    const float* whr  = (const float*)d_in[5];
    const float* br   = (const float*)d_in[6];
    const float* bw   = (const float*)d_in[7];
    const float* bb   = (const float*)d_in[8];
    const float* g1   = (const float*)d_in[9];
    const float* be1  = (const float*)d_in[10];
    const float* g2   = (const float*)d_in[11];
    const float* be2  = (const float*)d_in[12];
    const float* g3   = (const float*)d_in[13];
    const float* be3  = (const float*)d_in[14];
    const float* g4   = (const float*)d_in[15];
    const float* be4  = (const float*)d_in[16];
    const float* g5   = (const float*)d_in[17];
    const float* be5  = (const float*)d_in[18];
    const float* w2   = (const float*)d_in[19];
    const float* b2   = (const float*)d_in[20];
    const float* w3   = (const float*)d_in[21];
    const float* b3   = (const float*)d_in[22];
    const float* w4   = (const float*)d_in[23];
    const float* b4   = (const float*)d_in[24];
    const float* w5   = (const float*)d_in[25];
    const float* b5   = (const float*)d_in[26];
    const float* fcw  = (const float*)d_in[27];
    const float* fcb  = (const float*)d_in[28];
    float* out = (float*)d_out;

    k_zero<<<1, 256>>>();
    k_proj<<<dim3(259, 8), 256>>>(x, wif, wir, bf, br);
    k_lstm<<<dim3(32, 2), 256>>>(whf, whr);
    k_wave<<<dim3(32, 128), 128>>>(bw, bb);
    k_fold2<<<dim3(128, 3), 256>>>(g1, be1, w2, b2);
    k_conv2<<<dim3(9, 32), 256>>>();
    k_fold3<<<32, 256>>>(g2, be2, w3, b3);
    k_conv3<<<dim3(8, 32), 256>>>();
    k_bn3<<<2048, 256>>>(g3, be3);
    k_conv4<<<32, 256>>>(w4, b4);
    k_dwt<<<32, 128>>>();
    k_conv5<<<32, 256>>>(w5, b5);
    k_final<<<1, 512>>>(g4, be4, g5, be5, fcw, fcb, out);
}

// round 16
// speedup vs baseline: 1.0401x; 1.0122x over previous
#include <cuda_runtime.h>
#include <math.h>

#define NB 32
#define TT 518
#define NF 64
#define NG 512
#define CC 128
#define CW 768
#define L2C 516
#define VD 32
#define L3 512
#define L4 510

typedef unsigned long long u64;

__device__ float d_xg[NB * TT * NG];
__device__ float d_X[NB * CC * TT];
__device__ float d_wave[NB * CW * TT];
__device__ float d_st1[CW * 2];
__device__ float d_w2t[3 * 128 * CW];   // [k'][co][ci], BN1-folded
__device__ float d_b2p[128];
__device__ float d_c2[NB * 128 * L2C];
__device__ float d_st2[128 * 2];
__device__ float d_w3t[128 * VD * 5];   // [ci][co*5+k], BN2-folded
__device__ float d_b3p[VD];
__device__ float d_c3[NB * VD * L3];
__device__ float d_st3[VD * 2];
__device__ float d_ob[NB * VD * L3];
__device__ float d_dwt[NB * 5 * L3];
__device__ float d_P4[NB * 16], d_Q4[NB * 16];
__device__ float d_P5[NB * 16], d_Q5[NB * 16];

__device__ __forceinline__ float sigf(float x) {
    return __fdividef(1.f, 1.f + __expf(-x));
}
__device__ __forceinline__ float tanhfast(float x) {
    return 1.f - __fdividef(2.f, __expf(2.f * x) + 1.f);
}

// ---------- 0) zero stat accumulators + conv2 bias base + pooled sums ----------
__global__ __launch_bounds__(256) void k_zero()
{
    int i = threadIdx.x;
    for (int j = i; j < CW * 2; j += 256) d_st1[j] = 0.f;
    if (i < 256) d_st2[i] = 0.f;
    if (i < 64) d_st3[i] = 0.f;
    if (i < 128) d_b2p[i] = 0.f;
    for (int j = i; j < NB * 16; j += 256) {
        d_P4[j] = 0.f; d_Q4[j] = 0.f;
        d_P5[j] = 0.f; d_Q5[j] = 0.f;
    }
}

// ---------- 1) input projection ----------
__global__ __launch_bounds__(256) void k_proj(
    const float* __restrict__ x,
    const float* __restrict__ wif, const float* __restrict__ wir,
    const float* __restrict__ bf, const float* __restrict__ br)
{
    __shared__ float As[64 * 64];
    __shared__ float Bs[64 * 68];
    const int tid = threadIdx.x;
    const int m0 = blockIdx.x * 64, n0 = blockIdx.y * 64;
#pragma unroll
    for (int i = 0; i < 16; i++) {
        int idx = tid + i * 256;
        int k = idx >> 6, m = idx & 63;
        int mg = m0 + m, b = mg / TT, t = mg - b * TT;
        As[k * 64 + m] = x[(b * NF + k) * TT + t];
    }
#pragma unroll
    for (int i = 0; i < 16; i++) {
        int idx = tid + i * 256;
        int n = idx >> 6, k = idx & 63;
        int ng = n0 + n;
        Bs[k * 68 + n] = (ng < 256) ? wif[ng * 64 + k] : wir[(ng - 256) * 64 + k];
    }
    __syncthreads();
    const int mb = (tid >> 4) * 4, nb = (tid & 15) * 4;
    float acc[4][4];
#pragma unroll
    for (int i = 0; i < 4; i++)
#pragma unroll
        for (int j = 0; j < 4; j++) acc[i][j] = 0.f;
#pragma unroll
    for (int k = 0; k < 64; k++) {
        float4 a = *(const float4*)&As[k * 64 + mb];
        float4 bv = *(const float4*)&Bs[k * 68 + nb];
        float am[4] = {a.x, a.y, a.z, a.w};
        float bn[4] = {bv.x, bv.y, bv.z, bv.w};
#pragma unroll
        for (int mi = 0; mi < 4; mi++)
#pragma unroll
            for (int ni = 0; ni < 4; ni++) acc[mi][ni] += am[mi] * bn[ni];
    }
    float bvr[4];
#pragma unroll
    for (int ni = 0; ni < 4; ni++) {
        int ng = n0 + nb + ni;
        bvr[ni] = (ng < 256) ? bf[ng] : br[ng - 256];
    }
#pragma unroll
    for (int mi = 0; mi < 4; mi++) {
        int mg = m0 + mb + mi;
        float4 o = {acc[mi][0] + bvr[0], acc[mi][1] + bvr[1],
                    acc[mi][2] + bvr[2], acc[mi][3] + bvr[3]};
        *(float4*)&d_xg[(size_t)mg * NG + n0 + nb] = o;
    }
}

// ---------- 2) LSTM recurrence (packed f32x2, round-5 form) ----------
__global__ __launch_bounds__(256) void k_lstm(
    const float* __restrict__ whf, const float* __restrict__ whr)
{
    const int b = blockIdx.x, dir = blockIdx.y, tid = threadIdx.x;
    const float* __restrict__ whh = dir ? whr : whf;

    u64 w2[32];
    {
        const float2* wrow = (const float2*)(whh + tid * 64);
#pragma unroll
        for (int j = 0; j < 32; j++) {
            float2 p = wrow[j];
            asm("mov.b64 %0, {%1,%2};" : "=l"(w2[j]) : "f"(p.x), "f"(p.y));
        }
    }

    __shared__ __align__(16) float h_sh[64];
    __shared__ float g_sh[256];
    if (tid < 64) h_sh[tid] = 0.f;
    float c = 0.f;
    __syncthreads();

    const float* __restrict__ xg = d_xg + (size_t)b * TT * NG + dir * 256;
    int t = dir ? (TT - 1) : 0;
    const int dt = dir ? -1 : 1;
    float xv = xg[(size_t)t * NG + tid];

    for (int s = 0; s < TT; s++) {
        float xn = (s < TT - 1) ? xg[(size_t)(t + dt) * NG + tid] : 0.f;

        u64 acc0, acc1 = 0ULL;
        asm("mov.b64 %0, {%1,%2};" : "=l"(acc0) : "f"(xv), "f"(0.f));
        const u64* h2 = (const u64*)h_sh;
#pragma unroll
        for (int j = 0; j < 32; j += 2) {
            u64 hv0 = h2[j], hv1 = h2[j + 1];
            asm("fma.rn.f32x2 %0, %1, %2, %0;" : "+l"(acc0) : "l"(w2[j]), "l"(hv0));
            asm("fma.rn.f32x2 %0, %1, %2, %0;" : "+l"(acc1) : "l"(w2[j + 1]), "l"(hv1));
        }
        float a0, a1, b0, b1;
        asm("mov.b64 {%0,%1}, %2;" : "=f"(a0), "=f"(a1) : "l"(acc0));
        asm("mov.b64 {%0,%1}, %2;" : "=f"(b0), "=f"(b1) : "l"(acc1));
        g_sh[tid] = (a0 + b0) + (a1 + b1);
        __syncthreads();

        if (tid < 64) {
            float gi = g_sh[tid], gf = g_sh[64 + tid];
            float gg = g_sh[128 + tid], go = g_sh[192 + tid];
            c = sigf(gf) * c + sigf(gi) * tanhfast(gg);
            float h = sigf(go) * tanhfast(c);
            h_sh[tid] = h;
            d_X[((size_t)b * CC + dir * 64 + tid) * TT + t] = h;
        }
        __syncthreads();
        xv = xn;
        t += dt;
    }
}

// ---------- 3) wave module: 2 positions/thread (shared sw loads) + BN1 stats ----------
__global__ __launch_bounds__(128) void k_wave(
    const float* __restrict__ bw, const float* __restrict__ bb)
{
    __shared__ float xr[532];
    __shared__ float sw[90];
    __shared__ float sb[6];
    __shared__ float sRed[12];
    const int b = blockIdx.x, ch = blockIdx.y, tid = threadIdx.x;
    if (tid < 90) sw[tid] = bw[tid];
    if (tid < 6) sb[tid] = bb[tid];
    if (tid < 12) sRed[tid] = 0.f;
    const float* __restrict__ Xr = d_X + ((size_t)b * CC + ch) * TT;
    for (int i = tid; i < 532; i += 128) {
        int t = i - 7;
        xr[i] = (t >= 0 && t < TT) ? Xr[t] : 0.f;
    }
    __syncthreads();

    float zs[6], zq[6];
#pragma unroll
    for (int ii = 0; ii < 6; ii++) { zs[ii] = 0.f; zq[ii] = 0.f; }

    float* __restrict__ wrow = d_wave + ((size_t)b * CW + ch) * TT;

    for (int tb = tid * 2; tb < TT; tb += 256) {
        float win[16];
#pragma unroll
        for (int k = 0; k < 16; k++) win[k] = xr[tb + k];
        float pA[8], pB[8];
        pA[0] = win[7];
        pB[0] = win[8];
#pragma unroll
        for (int m = 1; m < 8; m++) {
            pA[m] = win[7 + m] + win[7 - m];
            pB[m] = win[8 + m] + win[8 - m];
        }
#pragma unroll 1
        for (int ii = 0; ii < 6; ii++) {
            float bias = sb[ii];
            float sA = bias, sB = bias;
#pragma unroll
            for (int k = 0; k < 15; k++) {
                float w = sw[ii * 15 + k];
                sA += win[k] * w;
                sB += win[k + 1] * w;
            }
            sA = fmaxf(sA, 0.f);
            sB = fmaxf(sB, 0.f);
            const float fscale = (6.283185307179586f / 15.f) * (float)(ii + 1);
            float cA = __cosf(fscale * sA);
            float cB = __cosf(fscale * sB);
            float oA = pA[0] + pA[1] * cA;
            float oB = pB[0] + pB[1] * cB;
            float cpA = cA, cppA = 1.f, cpB = cB, cppB = 1.f;
            float twoA = 2.f * cA, twoB = 2.f * cB;
#pragma unroll
            for (int m = 2; m < 8; m++) {
                float cmA = twoA * cpA - cppA;
                float cmB = twoB * cpB - cppB;
                oA += pA[m] * cmA;
                oB += pB[m] * cmB;
                cppA = cpA; cpA = cmA;
                cppB = cpB; cpB = cmB;
            }
            float qA = (truncf(sA * 15.f) + 1.f) * (2.f / 17.f);
            float qB = (truncf(sB * 15.f) + 1.f) * (2.f / 17.f);
            float zA = oA * rsqrtf(qA);
            float zB = oB * rsqrtf(qB);
            float* wr = wrow + (size_t)(ii * CC) * TT;
            wr[tb] = zA;
            wr[tb + 1] = zB;
            zs[ii] += zA + zB;
            zq[ii] += zA * zA + zB * zB;
        }
    }
    const int lane = tid & 31;
#pragma unroll
    for (int ii = 0; ii < 6; ii++) {
        float v1 = zs[ii], v2 = zq[ii];
#pragma unroll
        for (int o = 16; o > 0; o >>= 1) {
            v1 += __shfl_xor_sync(0xffffffffu, v1, o);
            v2 += __shfl_xor_sync(0xffffffffu, v2, o);
        }
        if (lane == 0) {
            atomicAdd(&sRed[ii * 2], v1);
            atomicAdd(&sRed[ii * 2 + 1], v2);
        }
    }
    __syncthreads();
    if (tid < 12)
        atomicAdd(&d_st1[2 * ((tid >> 1) * CC + ch) + (tid & 1)], sRed[tid]);
}

// ---------- fold BN1 into conv2, split over (co, k') ----------
__global__ __launch_bounds__(256) void k_fold2(
    const float* __restrict__ g1, const float* __restrict__ be1,
    const float* __restrict__ w2, const float* __restrict__ b2)
{
    const int co = blockIdx.x, k = blockIdx.y, tid = threadIdx.x;
    const float invN = 1.f / (float)(NB * TT);
    float acc = 0.f;
#pragma unroll
    for (int r = 0; r < 3; r++) {
        int ci = tid + r * 256;
        float m = d_st1[2 * ci] * invN;
        float v = d_st1[2 * ci + 1] * invN - m * m;
        float s = g1[ci] * rsqrtf(v + 1e-5f);
        float tt = be1[ci] - m * s;
        float wv = w2[(size_t)co * (CW * 3) + ci * 3 + k];
        d_w2t[(size_t)k * (128 * CW) + co * CW + ci] = wv * s;
        acc += wv * tt;
    }
    const int lane = tid & 31, wrp = tid >> 5;
#pragma unroll
    for (int o = 16; o > 0; o >>= 1) acc += __shfl_xor_sync(0xffffffffu, acc, o);
    __shared__ float red[8];
    if (lane == 0) red[wrp] = acc;
    __syncthreads();
    if (tid == 0) {
        float s = red[0] + red[1] + red[2] + red[3] + red[4] + red[5] + red[6] + red[7];
        if (k == 0) s += b2[co];
        atomicAdd(&d_b2p[co], s);
    }
}

// ---------- fold BN2 into conv3 ([ci][co*5+k] layout) ----------
__global__ __launch_bounds__(256) void k_fold3(
    const float* __restrict__ g2, const float* __restrict__ be2,
    const float* __restrict__ w3, const float* __restrict__ b3)
{
    __shared__ float s2[128], t2[128];
    const int co = blockIdx.x, tid = threadIdx.x;
    const float invN = 1.f / (float)(NB * L2C);
    if (tid < 128) {
        float m = d_st2[2 * tid] * invN;
        float v = d_st2[2 * tid + 1] * invN - m * m;
        float s = g2[tid] * rsqrtf(v + 1e-5f);
        s2[tid] = s;
        t2[tid] = be2[tid] - m * s;
    }
    __syncthreads();
    float acc = 0.f;
    for (int idx = tid; idx < 128 * 5; idx += 256) {
        int ci = idx / 5, k = idx - ci * 5;
        float wv = w3[(size_t)co * 640 + idx];
        d_w3t[(size_t)ci * 160 + co * 5 + k] = wv * s2[ci];
        acc += wv * t2[ci];
    }
    __shared__ float red[256];
    red[tid] = acc;
    __syncthreads();
    for (int o = 128; o > 0; o >>= 1) {
        if (tid < o) red[tid] += red[tid + o];
        __syncthreads();
    }
    if (tid == 0) d_b3p[co] = b3[co] + red[0];
}

// ---------- conv2 via tf32 mma.sync + relu + BN2 stats (R9 form) ----------
__global__ __launch_bounds__(256, 2) void k_conv2()
{
    __shared__ float As[128 * 36];
    __shared__ float Bs[32 * 72];
    __shared__ float sP2[128], sQ2[128];
    const int tid = threadIdx.x;
    const int wid = tid >> 5, lane = tid & 31;
    const int t0 = blockIdx.x * 64, b = blockIdx.y;
    const int mg = wid >> 1, ng = wid & 1;
    const int gr = lane >> 2, c = lane & 3;
    if (tid < 128) { sP2[tid] = 0.f; sQ2[tid] = 0.f; }

    float d[2][4][4];
#pragma unroll
    for (int mt = 0; mt < 2; mt++)
#pragma unroll
        for (int nt = 0; nt < 4; nt++)
#pragma unroll
            for (int r = 0; r < 4; r++) d[mt][nt][r] = 0.f;

    const float* __restrict__ wavB = d_wave + (size_t)b * CW * TT;
    const int ldco = tid >> 1, ldci = (tid & 1) * 16;
    const int ldn = tid & 63, ldk0 = (tid >> 6) * 8;
    const int tld = t0 + ldn;

    for (int kp = 0; kp < 3; kp++) {
        for (int cc = 0; cc < 24; cc++) {
            const int ci0 = cc * 32;
            __syncthreads();
            {
                const float4* src = (const float4*)&d_w2t[(size_t)kp * (128 * CW) + ldco * CW + ci0 + ldci];
                float4* dst = (float4*)&As[ldco * 36 + ldci];
                dst[0] = src[0]; dst[1] = src[1]; dst[2] = src[2]; dst[3] = src[3];
            }
            {
                int t = tld + kp;
                bool ok = (t < TT);
#pragma unroll
                for (int p = 0; p < 8; p++) {
                    int k = ldk0 + p;
                    Bs[k * 72 + ldn] = ok ? wavB[(size_t)(ci0 + k) * TT + t] : 0.f;
                }
            }
            __syncthreads();

            unsigned aR[2][2][8];
#pragma unroll
            for (int mt = 0; mt < 2; mt++) {
                int r0 = (mg * 32 + mt * 16 + gr) * 36 + c;
#pragma unroll
                for (int u = 0; u < 8; u++) {
                    aR[mt][0][u] = __float_as_uint(As[r0 + 4 * u]);
                    aR[mt][1][u] = __float_as_uint(As[r0 + 8 * 36 + 4 * u]);
                }
            }
#pragma unroll
            for (int s = 0; s < 4; s++) {
                unsigned bb[4][2];
#pragma unroll
                for (int nt = 0; nt < 4; nt++) {
                    int nn = ng * 32 + nt * 8 + gr;
                    bb[nt][0] = __float_as_uint(Bs[(c + 8 * s) * 72 + nn]);
                    bb[nt][1] = __float_as_uint(Bs[(c + 8 * s + 4) * 72 + nn]);
                }
#pragma unroll
                for (int mt = 0; mt < 2; mt++)
#pragma unroll
                    for (int nt = 0; nt < 4; nt++)
                        asm volatile(
                            "mma.sync.aligned.m16n8k8.row.col.f32.tf32.tf32.f32 "
                            "{%0,%1,%2,%3}, {%4,%5,%6,%7}, {%8,%9}, {%0,%1,%2,%3};"
                            : "+f"(d[mt][nt][0]), "+f"(d[mt][nt][1]),
                              "+f"(d[mt][nt][2]), "+f"(d[mt][nt][3])
                            : "r"(aR[mt][0][2 * s]), "r"(aR[mt][1][2 * s]),
                              "r"(aR[mt][0][2 * s + 1]), "r"(aR[mt][1][2 * s + 1]),
                              "r"(bb[nt][0]), "r"(bb[nt][1]));
            }
        }
    }

#pragma unroll
    for (int mt = 0; mt < 2; mt++) {
        int coA = mg * 32 + mt * 16 + gr;
        int coB = coA + 8;
        float bA = d_b2p[coA], bB = d_b2p[coB];
        float sA = 0.f, qA = 0.f, sB = 0.f, qB = 0.f;
        float* rowA = d_c2 + ((size_t)b * 128 + coA) * L2C;
        float* rowB = d_c2 + ((size_t)b * 128 + coB) * L2C;
#pragma unroll
        for (int nt = 0; nt < 4; nt++) {
            int tg = t0 + ng * 32 + nt * 8 + 2 * c;
            if (tg < L2C) {
                float z0 = fmaxf(d[mt][nt][0] + bA, 0.f);
                float z2 = fmaxf(d[mt][nt][2] + bB, 0.f);
                rowA[tg] = z0; rowB[tg] = z2;
                sA += z0; qA += z0 * z0;
                sB += z2; qB += z2 * z2;
            }
            if (tg + 1 < L2C) {
                float z1 = fmaxf(d[mt][nt][1] + bA, 0.f);
                float z3 = fmaxf(d[mt][nt][3] + bB, 0.f);
                rowA[tg + 1] = z1; rowB[tg + 1] = z3;
                sA += z1; qA += z1 * z1;
                sB += z3; qB += z3 * z3;
            }
        }
        atomicAdd(&sP2[coA], sA);
        atomicAdd(&sQ2[coA], qA);
        atomicAdd(&sP2[coB], sB);
        atomicAdd(&sQ2[coB], qB);
    }
    __syncthreads();
    if (tid < 128) {
        atomicAdd(&d_st2[2 * tid], sP2[tid]);
        atomicAdd(&d_st2[2 * tid + 1], sQ2[tid]);
    }
}

// ---------- conv3 (128->32, k=5) scalar + relu + BN3 stats ----------
__global__ __launch_bounds__(256) void k_conv3()
{
    __shared__ float xs[16 * 72];
    __shared__ float ws[16 * 160];
    __shared__ float sP3[32], sQ3[32];
    const int tid = threadIdx.x;
    const int t0 = blockIdx.x * 64, b = blockIdx.y;
    const int co_b = (tid >> 4) * 2, t_b = (tid & 15) * 4;
    if (tid < 32) { sP3[tid] = 0.f; sQ3[tid] = 0.f; }
    float acc[2][4];
#pragma unroll
    for (int i = 0; i < 2; i++)
#pragma unroll
        for (int j = 0; j < 4; j++) acc[i][j] = 0.f;

    for (int cc = 0; cc < 8; cc++) {
        for (int i = tid; i < 16 * 68; i += 256) {
            int ci = i / 68, j = i - ci * 68;
            xs[ci * 72 + j] = d_c2[((size_t)b * 128 + cc * 16 + ci) * L2C + t0 + j];
        }
        for (int i = tid; i < 2560; i += 256) {
            int ci = i / 160, r = i - ci * 160;
            ws[ci * 160 + r] = d_w3t[(size_t)(cc * 16 + ci) * 160 + r];
        }
        __syncthreads();
#pragma unroll
        for (int ci = 0; ci < 16; ci++) {
            float xv[8];
            float4 xa = *(const float4*)&xs[ci * 72 + t_b];
            float4 xb4 = *(const float4*)&xs[ci * 72 + t_b + 4];
            xv[0] = xa.x; xv[1] = xa.y; xv[2] = xa.z; xv[3] = xa.w;
            xv[4] = xb4.x; xv[5] = xb4.y; xv[6] = xb4.z; xv[7] = xb4.w;
            float wv[10];
#pragma unroll
            for (int j = 0; j < 10; j++) wv[j] = ws[ci * 160 + co_b * 5 + j];
#pragma unroll
            for (int cj = 0; cj < 2; cj++)
#pragma unroll
                for (int tj = 0; tj < 4; tj++) {
                    float s = acc[cj][tj];
#pragma unroll
                    for (int k = 0; k < 5; k++) s += wv[cj * 5 + k] * xv[tj + k];
                    acc[cj][tj] = s;
                }
        }
        __syncthreads();
    }
#pragma unroll
    for (int cj = 0; cj < 2; cj++) {
        int co = co_b + cj;
        float bias = d_b3p[co];
        float zsum = 0.f, zsq = 0.f;
#pragma unroll
        for (int tj = 0; tj < 4; tj++) {
            int t = t0 + t_b + tj;
            float z = fmaxf(acc[cj][tj] + bias, 0.f);
            d_c3[((size_t)b * VD + co) * L3 + t] = z;
            zsum += z; zsq += z * z;
        }
        atomicAdd(&sP3[co], zsum);
        atomicAdd(&sQ3[co], zsq);
    }
    __syncthreads();
    if (tid < 32) {
        atomicAdd(&d_st3[2 * tid], sP3[tid]);
        atomicAdd(&d_st3[2 * tid + 1], sQ3[tid]);
    }
}

// ---------- apply BN3 ----------
__global__ __launch_bounds__(256) void k_bn3(
    const float* __restrict__ g3, const float* __restrict__ be3)
{
    int i = blockIdx.x * 256 + threadIdx.x;
    int c = (i >> 9) & 31;
    const float invN = 1.f / (float)(NB * L3);
    float m = d_st3[2 * c] * invN;
    float v = d_st3[2 * c + 1] * invN - m * m;
    float s = g3[c] * rsqrtf(v + 1e-5f);
    d_ob[i] = (d_c3[i] - m) * s + be3[c];
}

// ---------- conv4 (32->16, k=3) + relu, pooled sums (split over l-chunks) ----------
__global__ __launch_bounds__(256) void k_conv4(
    const float* __restrict__ w4, const float* __restrict__ b4)
{
    __shared__ float wsh[1536];
    __shared__ float bsh[16];
    __shared__ float sP[16], sQ[16];
    const int b = blockIdx.x, chunk = blockIdx.y, tid = threadIdx.x;
    for (int i = tid; i < 1536; i += 256) wsh[i] = w4[i];
    if (tid < 16) { bsh[tid] = b4[tid]; sP[tid] = 0.f; sQ[tid] = 0.f; }
    __syncthreads();
    float ls[16], lq[16];
#pragma unroll
    for (int co = 0; co < 16; co++) { ls[co] = 0.f; lq[co] = 0.f; }
    const int l0 = chunk * 128;
    const int l1 = min(l0 + 128, L4);
    for (int l = l0 + tid; l < l1; l += 256) {
        float acc[16];
#pragma unroll
        for (int co = 0; co < 16; co++) acc[co] = 0.f;
        const float* __restrict__ xb = d_ob + (size_t)b * VD * L3 + l;
#pragma unroll 4
        for (int ci = 0; ci < 32; ci++) {
            float x0 = xb[ci * L3], x1 = xb[ci * L3 + 1], x2 = xb[ci * L3 + 2];
#pragma unroll
            for (int co = 0; co < 16; co++) {
                const float* w = &wsh[(co * 32 + ci) * 3];
                acc[co] += w[0] * x0 + w[1] * x1 + w[2] * x2;
            }
        }
#pragma unroll
        for (int co = 0; co < 16; co++) {
            float z = fmaxf(acc[co] + bsh[co], 0.f);
            ls[co] += z; lq[co] += z * z;
        }
    }
#pragma unroll
    for (int co = 0; co < 16; co++) {
        atomicAdd(&sP[co], ls[co]);
        atomicAdd(&sQ[co], lq[co]);
    }
    __syncthreads();
    if (tid < 16) {
        atomicAdd(&d_P4[b * 16 + tid], sP[tid]);
        atomicAdd(&d_Q4[b * 16 + tid], sQ[tid]);
    }
}

// ---------- DWT ----------
__global__ __launch_bounds__(128) void k_dwt()
{
    __shared__ float m[512];
    __shared__ float a1[256];
    __shared__ float a2[128];
    __shared__ float a3[64];
    const int b = blockIdx.x, tid = threadIdx.x;
    for (int l = tid; l < 512; l += 128) {
        float s = 0.f;
#pragma unroll 8
        for (int c = 0; c < 32; c++) s += d_ob[((size_t)b * VD + c) * L3 + l];
        m[l] = s * (1.f / 32.f);
    }
    __syncthreads();
    const float Hc = 0.7071067811865476f;
    float* __restrict__ dw = d_dwt + (size_t)b * 5 * L3;
    for (int i = tid; i < 256; i += 128) {
        float e = m[2 * i], o = m[2 * i + 1];
        a1[i] = (e + o) * Hc;
        float d = (e - o) * Hc;
        dw[4 * 512 + 2 * i] = d;
        dw[4 * 512 + 2 * i + 1] = d;
    }
    __syncthreads();
    if (tid < 128) {
        float e = a1[2 * tid], o = a1[2 * tid + 1];
        a2[tid] = (e + o) * Hc;
        float d = (e - o) * Hc;
#pragma unroll
        for (int j = 0; j < 4; j++) dw[3 * 512 + 4 * tid + j] = d;
    }
    __syncthreads();
    if (tid < 64) {
        float e = a2[2 * tid], o = a2[2 * tid + 1];
        a3[tid] = (e + o) * Hc;
        float d = (e - o) * Hc;
#pragma unroll
        for (int j = 0; j < 8; j++) dw[2 * 512 + 8 * tid + j] = d;
    }
    __syncthreads();
    if (tid < 32) {
        float e = a3[2 * tid], o = a3[2 * tid + 1];
        float a = (e + o) * Hc, d = (e - o) * Hc;
#pragma unroll
        for (int j = 0; j < 16; j++) {
            dw[16 * tid + j] = a;
            dw[512 + 16 * tid + j] = d;
        }
    }
}

// ---------- conv5 (5->16, k=3) + relu, pooled sums (split over l-chunks) ----------
__global__ __launch_bounds__(256) void k_conv5(
    const float* __restrict__ w5, const float* __restrict__ b5)
{
    __shared__ float wsh[240];
    __shared__ float bsh[16];
    __shared__ float sP[16], sQ[16];
    const int b = blockIdx.x, chunk = blockIdx.y, tid = threadIdx.x;
    if (tid < 240) wsh[tid] = w5[tid];
    if (tid < 16) { bsh[tid] = b5[tid]; sP[tid] = 0.f; sQ[tid] = 0.f; }
    __syncthreads();
    float ls[16], lq[16];
#pragma unroll
    for (int co = 0; co < 16; co++) { ls[co] = 0.f; lq[co] = 0.f; }
    const int l0 = chunk * 256;
    const int l1 = min(l0 + 256, L4);
    for (int l = l0 + tid; l < l1; l += 256) {
        float acc[16];
#pragma unroll
        for (int co = 0; co < 16; co++) acc[co] = 0.f;
        const float* __restrict__ xb = d_dwt + (size_t)b * 5 * L3 + l;
#pragma unroll
        for (int ci = 0; ci < 5; ci++) {
            float x0 = xb[ci * L3], x1 = xb[ci * L3 + 1], x2 = xb[ci * L3 + 2];
#pragma unroll
            for (int co = 0; co < 16; co++) {
                const float* w = &wsh[(co * 5 + ci) * 3];
                acc[co] += w[0] * x0 + w[1] * x1 + w[2] * x2;
            }
        }
#pragma unroll
        for (int co = 0; co < 16; co++) {
            float z = fmaxf(acc[co] + bsh[co], 0.f);
            ls[co] += z; lq[co] += z * z;
        }
    }
#pragma unroll
    for (int co = 0; co < 16; co++) {
        atomicAdd(&sP[co], ls[co]);
        atomicAdd(&sQ[co], lq[co]);
    }
    __syncthreads();
    if (tid < 16) {
        atomicAdd(&d_P5[b * 16 + tid], sP[tid]);
        atomicAdd(&d_Q5[b * 16 + tid], sQ[tid]);
    }
}

// ---------- final ----------
__global__ __launch_bounds__(512) void k_final(
    const float* __restrict__ g4, const float* __restrict__ be4,
    const float* __restrict__ g5, const float* __restrict__ be5,
    const float* __restrict__ fcw, const float* __restrict__ fcb,
    float* __restrict__ out)
{
    __shared__ float s4[16], t4[16], s5[16], t5[16], pool[512];
    const int tid = threadIdx.x;
    if (tid < 16) {
        float P = 0.f, Q = 0.f;
        for (int b = 0; b < NB; b++) { P += d_P4[b * 16 + tid]; Q += d_Q4[b * 16 + tid]; }
        const float N = (float)(NB * L4);
        float m = P / N, v = Q / N - m * m;
        float s = g4[tid] * rsqrtf(v + 1e-5f);
        s4[tid] = s;
        t4[tid] = be4[tid] - m * s;
    } else if (tid < 32) {
        int co = tid - 16;
        float P = 0.f, Q = 0.f;
        for (int b = 0; b < NB; b++) { P += d_P5[b * 16 + co]; Q += d_Q5[b * 16 + co]; }
        const float N = (float)(NB * L4);
        float m = P / N, v = Q / N - m * m;
        float s = g5[co] * rsqrtf(v + 1e-5f);
        s5[co] = s;
        t5[co] = be5[co] - m * s;
    }
    __syncthreads();
    {
        int b = tid >> 4, co = tid & 15;
        pool[tid] = (s4[co] * d_P4[b * 16 + co] + (float)L4 * t4[co]
                   + s5[co] * d_P5[b * 16 + co] + (float)L4 * t5[co]) * (1.f / (2.f * L4));
    }
    __syncthreads();
    if (tid < 320) {
        int b = tid / 10, j = tid - b * 10;
        float s = fcb[j];
#pragma unroll
        for (int co = 0; co < 16; co++) s += pool[b * 16 + co] * fcw[j * 16 + co];
        out[b * 10 + j] = s;
    }
}

extern "C" void kernel_launch(void* const* d_in, const int* in_sizes, int n_in,
                              void* d_out, int out_size)
{
    const float* x    = (const float*)d_in[0];
    const float* wif  = (const float*)d_in[1];
    const float* whf  = (const float*)d_in[2];
    const float* bf   = (const float*)d_in[3];
    const float* wir  = (const float*)d_in[4];
    const float* whr  = (const float*)d_in[5];
    const float* br   = (const float*)d_in[6];
    const float* bw   = (const float*)d_in[7];
    const float* bb   = (const float*)d_in[8];
    const float* g1   = (const float*)d_in[9];
    const float* be1  = (const float*)d_in[10];
    const float* g2   = (const float*)d_in[11];
    const float* be2  = (const float*)d_in[12];
    const float* g3   = (const float*)d_in[13];
    const float* be3  = (const float*)d_in[14];
    const float* g4   = (const float*)d_in[15];
    const float* be4  = (const float*)d_in[16];
    const float* g5   = (const float*)d_in[17];
    const float* be5  = (const float*)d_in[18];
    const float* w2   = (const float*)d_in[19];
    const float* b2   = (const float*)d_in[20];
    const float* w3   = (const float*)d_in[21];
    const float* b3   = (const float*)d_in[22];
    const float* w4   = (const float*)d_in[23];
    const float* b4   = (const float*)d_in[24];
    const float* w5   = (const float*)d_in[25];
    const float* b5   = (const float*)d_in[26];
    const float* fcw  = (const float*)d_in[27];
    const float* fcb  = (const float*)d_in[28];
    float* out = (float*)d_out;

    k_zero<<<1, 256>>>();
    k_proj<<<dim3(259, 8), 256>>>(x, wif, wir, bf, br);
    k_lstm<<<dim3(32, 2), 256>>>(whf, whr);
    k_wave<<<dim3(32, 128), 128>>>(bw, bb);
    k_fold2<<<dim3(128, 3), 256>>>(g1, be1, w2, b2);
    k_conv2<<<dim3(9, 32), 256>>>();
    k_fold3<<<32, 256>>>(g2, be2, w3, b3);
    k_conv3<<<dim3(8, 32), 256>>>();
    k_bn3<<<2048, 256>>>(g3, be3);
    k_conv4<<<dim3(32, 4), 256>>>(w4, b4);
    k_dwt<<<32, 128>>>();
    k_conv5<<<dim3(32, 2), 256>>>(w5, b5);
    k_final<<<1, 512>>>(g4, be4, g5, be5, fcw, fcb, out);
}